// round 1
// baseline (speedup 1.0000x reference)
#include <cuda_runtime.h>
#include <math.h>

// ---------------------------------------------------------------------------
// DictionaryMatchingTv — GB300 sm_103a
//   inputs (metadata order):
//     0: slice_signal  [N*16]  float32   (N = 36864)
//     1: db_mag        [D*16]  float32   (D = 4000)
//     2: db_t2s_s      [D]     float32
//     3: db_b1s        [D]     float32
//     4: delta_t_r2p_ms[16]    float32
//   output: [t2 (N) | b1 (N) | min_dist (N)] float32
// ---------------------------------------------------------------------------

#define ETL   16
#define MAXD  8192   // max dictionary atoms supported

__device__ int   g_M;                       // number of masked (SE) columns
__device__ int   g_cols[ETL];               // indices of masked columns
__device__ float g_pairs[(MAXD / 2) * 20];  // pair-interleaved compacted atoms
__device__ float g_full[MAXD * ETL];        // full normalized atoms (fallback)
__device__ float g_d2[MAXD];                // ||atom||^2 (fallback)

// ---- f32x2 packed helpers (Blackwell-only PTX) -----------------------------
__device__ __forceinline__ unsigned long long pkf(float lo, float hi) {
    unsigned long long r;
    asm("mov.b64 %0, {%1, %2};" : "=l"(r) : "f"(lo), "f"(hi));
    return r;
}
__device__ __forceinline__ unsigned long long pku(unsigned lo, unsigned hi) {
    unsigned long long r;
    asm("mov.b64 %0, {%1, %2};" : "=l"(r) : "r"(lo), "r"(hi));
    return r;
}
__device__ __forceinline__ void unpk(float& lo, float& hi, unsigned long long v) {
    asm("mov.b64 {%0, %1}, %2;" : "=f"(lo), "=f"(hi) : "l"(v));
}
__device__ __forceinline__ void mul2(unsigned long long& d, unsigned long long a,
                                     unsigned long long b) {
    asm("mul.rn.f32x2 %0, %1, %2;" : "=l"(d) : "l"(a), "l"(b));
}
__device__ __forceinline__ void fma2(unsigned long long& d, unsigned long long a,
                                     unsigned long long b) {
    asm("fma.rn.f32x2 %0, %1, %2, %0;" : "+l"(d) : "l"(a), "l"(b));
}

// ---------------------------------------------------------------------------
// Kernel 1: compute masked-column compaction table from delta_t_r2p_ms
// ---------------------------------------------------------------------------
__global__ void k_cols(const float* __restrict__ delta) {
    if (threadIdx.x == 0 && blockIdx.x == 0) {
        int m = 0;
        for (int e = 0; e < ETL; e++) {
            if (delta[e] * 1e-3f < 1e-3f) {
                if (m < ETL) g_cols[m] = e;
                m++;
            }
        }
        g_M = m;
    }
}

// ---------------------------------------------------------------------------
// Kernel 2: normalize dictionary atoms; build pair-interleaved compact table.
// Record layout per pair (20 floats, 80 B, 16B-aligned):
//   [j*2 + slot] = compacted value j of atom (2p+slot), j = 0..7 (zero-padded)
//   [16 + slot]  = d2 of atom  (pad atoms get 1e30 -> score = -5e29, never wins)
//   [18..19]     = padding
// ---------------------------------------------------------------------------
__global__ void k_atoms(const float* __restrict__ db_mag,
                        const float* __restrict__ delta, int D, int Dpad) {
    int a = blockIdx.x * blockDim.x + threadIdx.x;
    if (a >= Dpad) return;
    int pr = a >> 1, slot = a & 1;

    float c[8];
#pragma unroll
    for (int j = 0; j < 8; j++) c[j] = 0.0f;
    float d2 = 1e30f;  // padding atom sentinel

    if (a < D) {
        float w[ETL];
        float nn = 0.0f;
#pragma unroll
        for (int i = 0; i < ETL; i++) {
            float m = (delta[i] * 1e-3f < 1e-3f) ? 1.0f : 0.0f;
            float v = db_mag[a * ETL + i] * m;
            w[i] = v;
            nn += v * v;
        }
        nn = sqrtf(nn);
        float inv = (nn > 0.0f) ? 1.0f / nn : 0.0f;  // nan_to_num semantics
        float db[ETL];
        d2 = 0.0f;
#pragma unroll
        for (int i = 0; i < ETL; i++) {
            db[i] = w[i] * inv;
            d2 += db[i] * db[i];
            g_full[a * ETL + i] = db[i];
        }
        g_d2[a] = d2;
        int M = g_M;
        int mm = (M < 8) ? M : 8;
        for (int j = 0; j < mm; j++) c[j] = db[g_cols[j]];
    }

    float* rec = &g_pairs[pr * 20];
#pragma unroll
    for (int j = 0; j < 8; j++) rec[j * 2 + slot] = c[j];
    rec[16 + slot] = d2;
    if (slot == 0) { rec[18] = 0.0f; rec[19] = 0.0f; }
}

// ---------------------------------------------------------------------------
// Kernel 3: per-pixel dictionary match.
//   fast path (M <= 8): atoms staged in smem, f32x2 packed dot, 2 argmax streams
//   slow path (M  > 8): generic global-memory path (correctness fallback)
// score = dot - 0.5*d2  (argmax score == argmin dist^2); dist^2 = s2 - 2*score
// ---------------------------------------------------------------------------
__global__ void __launch_bounds__(256, 1)
k_match(const float* __restrict__ sig, const float* __restrict__ t2s,
        const float* __restrict__ b1s, const float* __restrict__ delta,
        float* __restrict__ out, int N, int D) {
    extern __shared__ float sm[];
    const int Dpad = (D + 1) & ~1;
    const int NP = Dpad >> 1;
    const int M = g_M;
    const bool fast = (M <= 8);

    if (fast) {  // stage pair table to shared (broadcast-read later)
        const int total4 = NP * 5;  // NP*20 floats / 4
        const uint4* src = (const uint4*)g_pairs;
        uint4* dst = (uint4*)sm;
        for (int i = threadIdx.x; i < total4; i += blockDim.x) dst[i] = src[i];
    }
    __syncthreads();

    int n = blockIdx.x * blockDim.x + threadIdx.x;
    if (n >= N) return;

    // ---- per-pixel signal normalize (two-step, matching reference) ----
    const float* spx = sig + (size_t)n * ETL;
    float v[ETL];
    float n1 = 0.0f;
#pragma unroll
    for (int i = 0; i < ETL; i++) { v[i] = spx[i]; n1 += v[i] * v[i]; }
    n1 = sqrtf(n1);
    float inv1 = (n1 > 0.0f) ? 1.0f / n1 : 0.0f;

    float best;
    int atom;
    float s2;

    if (fast) {
        float w[8];
        int mm = (M < 8) ? M : 8;
        float n2 = 0.0f;
#pragma unroll
        for (int j = 0; j < 8; j++) {
            float x = (j < mm) ? v[g_cols[j]] * inv1 : 0.0f;
            w[j] = x;
            n2 += x * x;
        }
        n2 = sqrtf(n2);
        float inv2 = (n2 > 0.0f) ? 1.0f / n2 : 0.0f;
        s2 = 0.0f;
        unsigned long long spk[8];
#pragma unroll
        for (int j = 0; j < 8; j++) {
            float s = w[j] * inv2;
            s2 += s * s;
            spk[j] = pkf(s, s);
        }
        const unsigned long long spD = pkf(-0.5f, -0.5f);

        float best0 = -INFINITY, best1 = -INFINITY;
        int bi0 = 0, bi1 = 0;

#pragma unroll 4
        for (int p = 0; p < NP; p++) {
            const float* rec = sm + p * 20;
            uint4 qa = *(const uint4*)(rec);
            uint4 qb = *(const uint4*)(rec + 4);
            uint4 qc = *(const uint4*)(rec + 8);
            uint4 qd = *(const uint4*)(rec + 12);
            unsigned long long dpk = *(const unsigned long long*)(rec + 16);

            unsigned long long a0 = pku(qa.x, qa.y), a1 = pku(qa.z, qa.w);
            unsigned long long a2 = pku(qb.x, qb.y), a3 = pku(qb.z, qb.w);
            unsigned long long a4 = pku(qc.x, qc.y), a5 = pku(qc.z, qc.w);
            unsigned long long a6 = pku(qd.x, qd.y), a7 = pku(qd.z, qd.w);

            unsigned long long acc;
            mul2(acc, a0, spk[0]);
            fma2(acc, a1, spk[1]);
            fma2(acc, a2, spk[2]);
            fma2(acc, a3, spk[3]);
            fma2(acc, a4, spk[4]);
            fma2(acc, a5, spk[5]);
            fma2(acc, a6, spk[6]);
            fma2(acc, a7, spk[7]);
            fma2(acc, dpk, spD);  // score = dot - 0.5*d2

            float se, so;
            unpk(se, so, acc);
            if (se > best0) { best0 = se; bi0 = p; }
            if (so > best1) { best1 = so; bi1 = p; }
        }
        // merge: even slot wins ties (lower atom index first, like jnp.argmin)
        if (best1 > best0) { best = best1; atom = 2 * bi1 + 1; }
        else               { best = best0; atom = 2 * bi0; }
    } else {
        // ---- generic fallback: any mask width, atoms from global ----
        float u[ETL];
        float n2 = 0.0f;
#pragma unroll
        for (int i = 0; i < ETL; i++) {
            float m = (delta[i] * 1e-3f < 1e-3f) ? 1.0f : 0.0f;
            u[i] = v[i] * inv1 * m;
            n2 += u[i] * u[i];
        }
        n2 = sqrtf(n2);
        float inv2 = (n2 > 0.0f) ? 1.0f / n2 : 0.0f;
        float s[ETL];
        s2 = 0.0f;
#pragma unroll
        for (int i = 0; i < ETL; i++) { s[i] = u[i] * inv2; s2 += s[i] * s[i]; }
        best = -INFINITY;
        atom = 0;
        for (int d = 0; d < D; d++) {
            float dot = 0.0f;
#pragma unroll
            for (int i = 0; i < ETL; i++) dot += g_full[d * ETL + i] * s[i];
            float sc = dot - 0.5f * g_d2[d];
            if (sc > best) { best = sc; atom = d; }
        }
    }

    if (atom >= D) atom = 0;  // padding safety (cannot actually win)
    float dist2 = s2 - 2.0f * best;
    float md = sqrtf(fmaxf(dist2, 0.0f));

    out[n]         = t2s[atom];
    out[N + n]     = b1s[atom];
    out[2 * N + n] = md;
}

// ---------------------------------------------------------------------------
extern "C" void kernel_launch(void* const* d_in, const int* in_sizes, int n_in,
                              void* d_out, int out_size) {
    const float* sig   = (const float*)d_in[0];
    const float* dbmag = (const float*)d_in[1];
    const float* t2s   = (const float*)d_in[2];
    const float* b1s   = (const float*)d_in[3];
    const float* delta = (const float*)d_in[4];

    const int D = in_sizes[2];                 // 4000
    const int N = in_sizes[0] / ETL;           // 36864
    const int Dpad = (D + 1) & ~1;
    const size_t smem = (size_t)(Dpad / 2) * 20 * sizeof(float);  // 160 KB

    cudaFuncSetAttribute(k_match, cudaFuncAttributeMaxDynamicSharedMemorySize,
                         (int)smem);

    k_cols<<<1, 1>>>(delta);
    k_atoms<<<(Dpad + 127) / 128, 128>>>(dbmag, delta, D, Dpad);
    int blocks = (N + 255) / 256;
    k_match<<<blocks, 256, smem>>>(sig, t2s, b1s, delta, (float*)d_out, N, D);
}